// round 1
// baseline (speedup 1.0000x reference)
#include <cuda_runtime.h>
#include <cuda_bf16.h>
#include <cstdio>

#define NN 30000
#define NE 240000
#define NE2 (NE + NN)
#define D1 512   // heads*hid layer1
#define D2 128   // heads*out2 layer2
#define H 2
#define C1 256
#define C2 64
#define NCLS 20
#define EPS 1e-5f
#define NEG 0.2f

// ---------------- scratch (device globals; no allocations) ----------------
__device__ float g_xl1[(size_t)NN * D1];
__device__ float g_xr1[(size_t)NN * D1];
__device__ float g_acc1[(size_t)NN * D1];
__device__ float g_xl2[(size_t)NN * D2];
__device__ float g_xr2[(size_t)NN * D2];
__device__ float g_acc2[(size_t)NN * D2];
__device__ float g_expv[(size_t)NE2 * H];
__device__ float g_den1[(size_t)NN * H];
__device__ float g_den2[(size_t)NN * H];
__device__ float g_cnt[NN];
__device__ float g_lattr[NN];   // edge-attr sum -> loop_attr (in place)

// ---------------- utility ----------------
__global__ void zero_k(float* p, int n) {
    for (int i = blockIdx.x * blockDim.x + threadIdx.x; i < n; i += gridDim.x * blockDim.x)
        p[i] = 0.f;
}

__global__ void edge_count_k(const int* __restrict__ dst, const float* __restrict__ eattr,
                             float* __restrict__ cnt, float* __restrict__ asum, int E) {
    int e = blockIdx.x * blockDim.x + threadIdx.x;
    if (e < E) {
        int d = dst[e];
        atomicAdd(&cnt[d], 1.f);
        atomicAdd(&asum[d], eattr[e]);
    }
}

__global__ void loop_attr_k(float* __restrict__ asum, const float* __restrict__ cnt, int n) {
    int i = blockIdx.x * blockDim.x + threadIdx.x;
    if (i < n) asum[i] = asum[i] / fmaxf(cnt[i], 1.f);
}

// ---------------- SGEMM: C[M,N] = A[M,K] @ B[N,K]^T + bias[N] ----------------
#define TS 64
#define KT 16
__global__ void sgemm_bias_k(const float* __restrict__ A, const float* __restrict__ B,
                             const float* __restrict__ bias, float* __restrict__ C,
                             int M, int N, int K) {
    __shared__ float As[KT][TS + 1];
    __shared__ float Bs[KT][TS + 1];
    int tx = threadIdx.x % 16, ty = threadIdx.x / 16;
    int bm = blockIdx.y * TS, bn = blockIdx.x * TS;
    float acc[4][4] = {};
    for (int k0 = 0; k0 < K; k0 += KT) {
        for (int i = threadIdx.x; i < TS * KT; i += 256) {
            int m = i / KT, k = i % KT;
            int gm = bm + m;
            As[k][m] = (gm < M) ? A[(size_t)gm * K + k0 + k] : 0.f;
        }
        for (int i = threadIdx.x; i < TS * KT; i += 256) {
            int nn = i / KT, k = i % KT;
            int gn = bn + nn;
            Bs[k][nn] = (gn < N) ? B[(size_t)gn * K + k0 + k] : 0.f;
        }
        __syncthreads();
#pragma unroll
        for (int k = 0; k < KT; k++) {
            float a[4], b[4];
#pragma unroll
            for (int i = 0; i < 4; i++) a[i] = As[k][ty * 4 + i];
#pragma unroll
            for (int j = 0; j < 4; j++) b[j] = Bs[k][tx * 4 + j];
#pragma unroll
            for (int i = 0; i < 4; i++)
#pragma unroll
                for (int j = 0; j < 4; j++) acc[i][j] += a[i] * b[j];
        }
        __syncthreads();
    }
#pragma unroll
    for (int i = 0; i < 4; i++) {
        int m = bm + ty * 4 + i;
        if (m >= M) continue;
#pragma unroll
        for (int j = 0; j < 4; j++) {
            int n = bn + tx * 4 + j;
            if (n >= N) continue;
            C[(size_t)m * N + n] = acc[i][j] + bias[n];
        }
    }
}

// ---------------- edge logits + exp + denom (warp per (edge,head)) ----------------
__global__ void logits_k(const int* __restrict__ src, const int* __restrict__ dst,
                         const float* __restrict__ eattr, const float* __restrict__ lattr,
                         const float* __restrict__ xl, const float* __restrict__ xr,
                         const float* __restrict__ We, const float* __restrict__ att,
                         float* __restrict__ expv, float* __restrict__ denom,
                         int E, int N, int C) {
    int gw = (blockIdx.x * blockDim.x + threadIdx.x) >> 5;
    int lane = threadIdx.x & 31;
    int total = (E + N) * H;
    if (gw >= total) return;
    int h = gw % H;
    int e = gw / H;
    int s, d;
    float ea;
    if (e < E) { s = src[e]; d = dst[e]; ea = eattr[e]; }
    else       { s = d = e - E; ea = lattr[s]; }
    int Dd = H * C;
    const float* xls = xl + (size_t)s * Dd + h * C;
    const float* xrd = xr + (size_t)d * Dd + h * C;
    const float* Weh = We + h * C;
    const float* ath = att + h * C;
    float acc = 0.f;
    for (int c = lane; c < C; c += 32) {
        float v = xls[c] + xrd[c] + ea * Weh[c];
        v = (v > 0.f) ? v : NEG * v;
        acc += v * ath[c];
    }
#pragma unroll
    for (int o = 16; o > 0; o >>= 1) acc += __shfl_down_sync(0xffffffffu, acc, o);
    if (lane == 0) {
        float p = __expf(acc);   // segment-max dropped: mathematically identical softmax
        expv[(size_t)e * H + h] = p;
        atomicAdd(&denom[(size_t)d * H + h], p);
    }
}

// ---------------- weighted scatter-add (warp per (edge,head)) ----------------
__global__ void aggregate_k(const int* __restrict__ src, const int* __restrict__ dst,
                            const float* __restrict__ xl, const float* __restrict__ expv,
                            const float* __restrict__ denom, float* __restrict__ out,
                            int E, int N, int C) {
    int gw = (blockIdx.x * blockDim.x + threadIdx.x) >> 5;
    int lane = threadIdx.x & 31;
    int total = (E + N) * H;
    if (gw >= total) return;
    int h = gw % H;
    int e = gw / H;
    int s, d;
    if (e < E) { s = src[e]; d = dst[e]; }
    else       { s = d = e - E; }
    float alpha = expv[(size_t)e * H + h] / denom[(size_t)d * H + h];
    int Dd = H * C;
    const float* xls = xl + (size_t)s * Dd + h * C;
    float* od = out + (size_t)d * Dd + h * C;
    for (int c = lane; c < C; c += 32)
        atomicAdd(&od[c], alpha * xls[c]);
}

// ---------------- bias + (silu) + rmsnorm, one block per node ----------------
__global__ void postact_rms_k(const float* __restrict__ acc, const float* __restrict__ bias,
                              const float* __restrict__ w, float* __restrict__ out,
                              int D, int do_silu) {
    int n = blockIdx.x;
    float vals[2];
    float ss = 0.f;
    int nv = 0;
    for (int j = threadIdx.x; j < D; j += blockDim.x) {
        float v = acc[(size_t)n * D + j] + bias[j];
        if (do_silu) v = v / (1.f + __expf(-v));
        vals[nv++] = v;
        ss += v * v;
    }
    __shared__ float red[32];
    int lane = threadIdx.x & 31, wid = threadIdx.x >> 5;
#pragma unroll
    for (int o = 16; o > 0; o >>= 1) ss += __shfl_down_sync(0xffffffffu, ss, o);
    if (lane == 0) red[wid] = ss;
    __syncthreads();
    if (wid == 0) {
        float s2 = (lane < (blockDim.x >> 5)) ? red[lane] : 0.f;
#pragma unroll
        for (int o = 16; o > 0; o >>= 1) s2 += __shfl_down_sync(0xffffffffu, s2, o);
        if (lane == 0) red[0] = s2;
    }
    __syncthreads();
    float inv = rsqrtf(red[0] / (float)D + EPS);
    nv = 0;
    for (int j = threadIdx.x; j < D; j += blockDim.x)
        out[(size_t)n * D + j] = vals[nv++] * inv * w[j];
}

// ---------------- classifier: out[N,20] = h[N,128] @ W[20,128]^T ----------------
__global__ void out_gemm_k(const float* __restrict__ h, const float* __restrict__ W,
                           float* __restrict__ out, int N, int K, int Cn) {
    extern __shared__ float Ws[];
    for (int i = threadIdx.x; i < Cn * K; i += blockDim.x) Ws[i] = W[i];
    __syncthreads();
    int idx = blockIdx.x * blockDim.x + threadIdx.x;
    if (idx >= N * Cn) return;
    int n = idx / Cn, c = idx % Cn;
    const float* hr = h + (size_t)n * K;
    const float* wr = Ws + c * K;
    float s = 0.f;
#pragma unroll 8
    for (int k = 0; k < K; k++) s += hr[k] * wr[k];
    out[idx] = s;
}

// ---------------- launch ----------------
static void* sym(const void* s) {
    void* p = nullptr;
    cudaGetSymbolAddress(&p, s);
    return p;
}

extern "C" void kernel_launch(void* const* d_in, const int* in_sizes, int n_in,
                              void* d_out, int out_size) {
    const float* x     = (const float*)d_in[0];
    const int*   ei    = (const int*)d_in[1];   // [2, NE]
    const float* eattr = (const float*)d_in[2]; // [NE, 1]
    const float* Wl1   = (const float*)d_in[3];
    const float* bl1   = (const float*)d_in[4];
    const float* Wr1   = (const float*)d_in[5];
    const float* br1   = (const float*)d_in[6];
    const float* We1   = (const float*)d_in[7];
    const float* att1  = (const float*)d_in[8];
    const float* bias1 = (const float*)d_in[9];
    const float* Wl2   = (const float*)d_in[10];
    const float* bl2   = (const float*)d_in[11];
    const float* Wr2   = (const float*)d_in[12];
    const float* br2   = (const float*)d_in[13];
    const float* We2   = (const float*)d_in[14];
    const float* att2  = (const float*)d_in[15];
    const float* bias2 = (const float*)d_in[16];
    const float* w_ln1 = (const float*)d_in[17];
    const float* w_ln3 = (const float*)d_in[18];
    const float* W_out = (const float*)d_in[19];
    float* out = (float*)d_out;

    const int* srcp = ei;
    const int* dstp = ei + NE;

    float* xl1  = (float*)sym(g_xl1);
    float* xr1  = (float*)sym(g_xr1);
    float* acc1 = (float*)sym(g_acc1);
    float* xl2  = (float*)sym(g_xl2);
    float* xr2  = (float*)sym(g_xr2);
    float* acc2 = (float*)sym(g_acc2);
    float* expv = (float*)sym(g_expv);
    float* den1 = (float*)sym(g_den1);
    float* den2 = (float*)sym(g_den2);
    float* cnt  = (float*)sym(g_cnt);
    float* latt = (float*)sym(g_lattr);

    // --- zero accumulators ---
    zero_k<<<2048, 256>>>(acc1, NN * D1);
    zero_k<<<1024, 256>>>(acc2, NN * D2);
    zero_k<<<64, 256>>>(den1, NN * H);
    zero_k<<<64, 256>>>(den2, NN * H);
    zero_k<<<64, 256>>>(cnt, NN);
    zero_k<<<64, 256>>>(latt, NN);

    // --- self-loop attr: per-dst mean of incoming edge attrs ---
    edge_count_k<<<(NE + 255) / 256, 256>>>(dstp, eattr, cnt, latt, NE);
    loop_attr_k<<<(NN + 255) / 256, 256>>>(latt, cnt, NN);

    // --- layer 1 node transforms ---
    dim3 g1((D1 + TS - 1) / TS, (NN + TS - 1) / TS);
    sgemm_bias_k<<<g1, 256>>>(x, Wl1, bl1, xl1, NN, D1, D2);  // K = 128
    sgemm_bias_k<<<g1, 256>>>(x, Wr1, br1, xr1, NN, D1, D2);

    // --- layer 1 attention ---
    int nwarp = NE2 * H;
    int nblk = (nwarp * 32 + 255) / 256;
    logits_k<<<nblk, 256>>>(srcp, dstp, eattr, latt, xl1, xr1, We1, att1, expv, den1, NE, NN, C1);
    aggregate_k<<<nblk, 256>>>(srcp, dstp, xl1, expv, den1, acc1, NE, NN, C1);

    // --- silu + rmsnorm (in place) ---
    postact_rms_k<<<NN, 256>>>(acc1, bias1, w_ln1, acc1, D1, 1);

    // --- layer 2 node transforms (K = 512) ---
    dim3 g2((D2 + TS - 1) / TS, (NN + TS - 1) / TS);
    sgemm_bias_k<<<g2, 256>>>(acc1, Wl2, bl2, xl2, NN, D2, D1);
    sgemm_bias_k<<<g2, 256>>>(acc1, Wr2, br2, xr2, NN, D2, D1);

    // --- layer 2 attention ---
    logits_k<<<nblk, 256>>>(srcp, dstp, eattr, latt, xl2, xr2, We2, att2, expv, den2, NE, NN, C2);
    aggregate_k<<<nblk, 256>>>(srcp, dstp, xl2, expv, den2, acc2, NE, NN, C2);

    // --- bias + rmsnorm (no silu) ---
    postact_rms_k<<<NN, 256>>>(acc2, bias2, w_ln3, acc2, D2, 0);

    // --- classifier ---
    int ntot = NN * NCLS;
    out_gemm_k<<<(ntot + 255) / 256, 256, NCLS * D2 * sizeof(float)>>>(acc2, W_out, out, NN, D2, NCLS);
}

// round 2
// speedup vs baseline: 1.3719x; 1.3719x over previous
#include <cuda_runtime.h>
#include <cuda_bf16.h>

#define NN 30000
#define NE 240000
#define NE2 (NE + NN)
#define D1 512
#define D2 128
#define H 2
#define C1 256
#define C2 64
#define NCLS 20
#define EPS 1e-5f
#define NEG 0.2f

// ---------------- scratch (device globals; no allocations) ----------------
__device__ float g_xl1[(size_t)NN * D1];
__device__ float g_xr1[(size_t)NN * D1];
__device__ float g_acc1[(size_t)NN * D1];
__device__ float g_xl2[(size_t)NN * D2];
__device__ float g_xr2[(size_t)NN * D2];
__device__ float g_acc2[(size_t)NN * D2];
__device__ float g_expv[(size_t)NE2 * H];
__device__ float g_den1[(size_t)NN * H];
__device__ float g_den2[(size_t)NN * H];
__device__ float g_cnt[NN];
__device__ float g_lattr[NN];

// ---------------- utility ----------------
__global__ void zero_k(float* p, int n) {
    for (int i = blockIdx.x * blockDim.x + threadIdx.x; i < n; i += gridDim.x * blockDim.x)
        p[i] = 0.f;
}

__global__ void edge_count_k(const int* __restrict__ dst, const float* __restrict__ eattr,
                             float* __restrict__ cnt, float* __restrict__ asum, int E) {
    int e = blockIdx.x * blockDim.x + threadIdx.x;
    if (e < E) {
        int d = dst[e];
        atomicAdd(&cnt[d], 1.f);
        atomicAdd(&asum[d], eattr[e]);
    }
}

__global__ void loop_attr_k(float* __restrict__ asum, const float* __restrict__ cnt, int n) {
    int i = blockIdx.x * blockDim.x + threadIdx.x;
    if (i < n) asum[i] = asum[i] / fmaxf(cnt[i], 1.f);
}

// ---------------- TF32 helpers ----------------
__device__ __forceinline__ unsigned f2tf32(float f) {
    unsigned r;
    asm("cvt.rna.tf32.f32 %0, %1;" : "=r"(r) : "f"(f));
    return r;
}
__device__ __forceinline__ void split_tf32(float f, unsigned& hi, unsigned& lo) {
    hi = f2tf32(f);
    lo = f2tf32(f - __uint_as_float(hi));
}
__device__ __forceinline__ void mma_tf32(float* c, const unsigned* a, const unsigned* b) {
    asm volatile(
        "mma.sync.aligned.m16n8k8.row.col.f32.tf32.tf32.f32 "
        "{%0,%1,%2,%3}, {%4,%5,%6,%7}, {%8,%9}, {%0,%1,%2,%3};\n"
        : "+f"(c[0]), "+f"(c[1]), "+f"(c[2]), "+f"(c[3])
        : "r"(a[0]), "r"(a[1]), "r"(a[2]), "r"(a[3]), "r"(b[0]), "r"(b[1]));
}

// ---------------- TC GEMM: C[M,N] = A[M,K] @ B[N,K]^T + bias[N] ----------------
// block 128x64, 256 threads (8 warps, warp tile 32x32), BK=16, 3xTF32 split.
// Requires: N % 64 == 0, K % 16 == 0.
__global__ __launch_bounds__(256) void gemm_tc_k(
    const float* __restrict__ A, const float* __restrict__ B,
    const float* __restrict__ bias, float* __restrict__ C,
    int M, int N, int K) {
    __shared__ float As[128][20];
    __shared__ float Bs[64][20];

    const int tid = threadIdx.x;
    const int lane = tid & 31;
    const int warp = tid >> 5;
    const int wm = warp >> 1;       // 0..3
    const int wn = warp & 1;        // 0..1
    const int groupID = lane >> 2;  // 0..7
    const int tg = lane & 3;        // 0..3

    const int bm = blockIdx.y * 128;
    const int bn = blockIdx.x * 64;

    float acc[2][4][4] = {};

    for (int k0 = 0; k0 < K; k0 += 16) {
        // load A tile 128x16 (float4, clamp rows at M)
#pragma unroll
        for (int i = 0; i < 2; i++) {
            int idx = tid + i * 256;          // 0..511
            int m = idx >> 2;
            int k4 = idx & 3;
            int gm = bm + m;
            if (gm >= M) gm = M - 1;
            float4 v = *(const float4*)&A[(size_t)gm * K + k0 + k4 * 4];
            As[m][k4 * 4 + 0] = v.x;
            As[m][k4 * 4 + 1] = v.y;
            As[m][k4 * 4 + 2] = v.z;
            As[m][k4 * 4 + 3] = v.w;
        }
        // load B tile 64x16
        {
            int n = tid >> 2;
            int k4 = tid & 3;
            float4 v = *(const float4*)&B[(size_t)(bn + n) * K + k0 + k4 * 4];
            Bs[n][k4 * 4 + 0] = v.x;
            Bs[n][k4 * 4 + 1] = v.y;
            Bs[n][k4 * 4 + 2] = v.z;
            Bs[n][k4 * 4 + 3] = v.w;
        }
        __syncthreads();

#pragma unroll
        for (int ks = 0; ks < 16; ks += 8) {
            unsigned ahi[2][4], alo[2][4], bhi[4][2], blo[4][2];
#pragma unroll
            for (int mt = 0; mt < 2; mt++) {
                int r = wm * 32 + mt * 16 + groupID;
                float f0 = As[r][ks + tg];
                float f1 = As[r + 8][ks + tg];
                float f2 = As[r][ks + tg + 4];
                float f3 = As[r + 8][ks + tg + 4];
                split_tf32(f0, ahi[mt][0], alo[mt][0]);
                split_tf32(f1, ahi[mt][1], alo[mt][1]);
                split_tf32(f2, ahi[mt][2], alo[mt][2]);
                split_tf32(f3, ahi[mt][3], alo[mt][3]);
            }
#pragma unroll
            for (int nt = 0; nt < 4; nt++) {
                int n = wn * 32 + nt * 8 + groupID;
                float f0 = Bs[n][ks + tg];
                float f1 = Bs[n][ks + tg + 4];
                split_tf32(f0, bhi[nt][0], blo[nt][0]);
                split_tf32(f1, bhi[nt][1], blo[nt][1]);
            }
#pragma unroll
            for (int mt = 0; mt < 2; mt++)
#pragma unroll
                for (int nt = 0; nt < 4; nt++) {
                    mma_tf32(acc[mt][nt], ahi[mt], bhi[nt]);
                    mma_tf32(acc[mt][nt], alo[mt], bhi[nt]);
                    mma_tf32(acc[mt][nt], ahi[mt], blo[nt]);
                }
        }
        __syncthreads();
    }

    // epilogue: C += bias
#pragma unroll
    for (int mt = 0; mt < 2; mt++) {
        int row0 = bm + wm * 32 + mt * 16 + groupID;
#pragma unroll
        for (int nt = 0; nt < 4; nt++) {
            int col0 = bn + wn * 32 + nt * 8 + tg * 2;
            float b0 = bias[col0], b1 = bias[col0 + 1];
            if (row0 < M) {
                C[(size_t)row0 * N + col0] = acc[mt][nt][0] + b0;
                C[(size_t)row0 * N + col0 + 1] = acc[mt][nt][1] + b1;
            }
            if (row0 + 8 < M) {
                C[(size_t)(row0 + 8) * N + col0] = acc[mt][nt][2] + b0;
                C[(size_t)(row0 + 8) * N + col0 + 1] = acc[mt][nt][3] + b1;
            }
        }
    }
}

// ---------------- edge logits + exp + denom (warp per (edge,head)) ----------------
__global__ void logits_k(const int* __restrict__ src, const int* __restrict__ dst,
                         const float* __restrict__ eattr, const float* __restrict__ lattr,
                         const float* __restrict__ xl, const float* __restrict__ xr,
                         const float* __restrict__ We, const float* __restrict__ att,
                         float* __restrict__ expv, float* __restrict__ denom,
                         int E, int N, int C) {
    int gw = (blockIdx.x * blockDim.x + threadIdx.x) >> 5;
    int lane = threadIdx.x & 31;
    int total = (E + N) * H;
    if (gw >= total) return;
    int h = gw % H;
    int e = gw / H;
    int s, d;
    float ea;
    if (e < E) { s = src[e]; d = dst[e]; ea = eattr[e]; }
    else       { s = d = e - E; ea = lattr[s]; }
    int Dd = H * C;
    const float* xls = xl + (size_t)s * Dd + h * C;
    const float* xrd = xr + (size_t)d * Dd + h * C;
    const float* Weh = We + h * C;
    const float* ath = att + h * C;
    float acc = 0.f;
    for (int c = lane; c < C; c += 32) {
        float v = xls[c] + xrd[c] + ea * Weh[c];
        v = (v > 0.f) ? v : NEG * v;
        acc += v * ath[c];
    }
#pragma unroll
    for (int o = 16; o > 0; o >>= 1) acc += __shfl_down_sync(0xffffffffu, acc, o);
    if (lane == 0) {
        float p = __expf(acc);
        expv[(size_t)e * H + h] = p;
        atomicAdd(&denom[(size_t)d * H + h], p);
    }
}

// ---------------- weighted scatter-add (warp per (edge,head)) ----------------
__global__ void aggregate_k(const int* __restrict__ src, const int* __restrict__ dst,
                            const float* __restrict__ xl, const float* __restrict__ expv,
                            const float* __restrict__ denom, float* __restrict__ out,
                            int E, int N, int C) {
    int gw = (blockIdx.x * blockDim.x + threadIdx.x) >> 5;
    int lane = threadIdx.x & 31;
    int total = (E + N) * H;
    if (gw >= total) return;
    int h = gw % H;
    int e = gw / H;
    int s, d;
    if (e < E) { s = src[e]; d = dst[e]; }
    else       { s = d = e - E; }
    float alpha = expv[(size_t)e * H + h] / denom[(size_t)d * H + h];
    int Dd = H * C;
    const float* xls = xl + (size_t)s * Dd + h * C;
    float* od = out + (size_t)d * Dd + h * C;
    for (int c = lane; c < C; c += 32)
        atomicAdd(&od[c], alpha * xls[c]);
}

// ---------------- bias + (silu) + rmsnorm, one block per node ----------------
__global__ void postact_rms_k(const float* __restrict__ acc, const float* __restrict__ bias,
                              const float* __restrict__ w, float* __restrict__ out,
                              int D, int do_silu) {
    int n = blockIdx.x;
    float vals[2];
    float ss = 0.f;
    int nv = 0;
    for (int j = threadIdx.x; j < D; j += blockDim.x) {
        float v = acc[(size_t)n * D + j] + bias[j];
        if (do_silu) v = v / (1.f + __expf(-v));
        vals[nv++] = v;
        ss += v * v;
    }
    __shared__ float red[32];
    int lane = threadIdx.x & 31, wid = threadIdx.x >> 5;
#pragma unroll
    for (int o = 16; o > 0; o >>= 1) ss += __shfl_down_sync(0xffffffffu, ss, o);
    if (lane == 0) red[wid] = ss;
    __syncthreads();
    if (wid == 0) {
        float s2 = (lane < (blockDim.x >> 5)) ? red[lane] : 0.f;
#pragma unroll
        for (int o = 16; o > 0; o >>= 1) s2 += __shfl_down_sync(0xffffffffu, s2, o);
        if (lane == 0) red[0] = s2;
    }
    __syncthreads();
    float inv = rsqrtf(red[0] / (float)D + EPS);
    nv = 0;
    for (int j = threadIdx.x; j < D; j += blockDim.x)
        out[(size_t)n * D + j] = vals[nv++] * inv * w[j];
}

// ---------------- classifier: out[N,20] = h[N,128] @ W[20,128]^T ----------------
__global__ void out_gemm_k(const float* __restrict__ h, const float* __restrict__ W,
                           float* __restrict__ out, int N, int K, int Cn) {
    extern __shared__ float Ws[];
    for (int i = threadIdx.x; i < Cn * K; i += blockDim.x) Ws[i] = W[i];
    __syncthreads();
    int idx = blockIdx.x * blockDim.x + threadIdx.x;
    if (idx >= N * Cn) return;
    int n = idx / Cn, c = idx % Cn;
    const float* hr = h + (size_t)n * K;
    const float* wr = Ws + c * K;
    float s = 0.f;
#pragma unroll 8
    for (int k = 0; k < K; k++) s += hr[k] * wr[k];
    out[idx] = s;
}

// ---------------- launch ----------------
static void* sym(const void* s) {
    void* p = nullptr;
    cudaGetSymbolAddress(&p, s);
    return p;
}

extern "C" void kernel_launch(void* const* d_in, const int* in_sizes, int n_in,
                              void* d_out, int out_size) {
    const float* x     = (const float*)d_in[0];
    const int*   ei    = (const int*)d_in[1];
    const float* eattr = (const float*)d_in[2];
    const float* Wl1   = (const float*)d_in[3];
    const float* bl1   = (const float*)d_in[4];
    const float* Wr1   = (const float*)d_in[5];
    const float* br1   = (const float*)d_in[6];
    const float* We1   = (const float*)d_in[7];
    const float* att1  = (const float*)d_in[8];
    const float* bias1 = (const float*)d_in[9];
    const float* Wl2   = (const float*)d_in[10];
    const float* bl2   = (const float*)d_in[11];
    const float* Wr2   = (const float*)d_in[12];
    const float* br2   = (const float*)d_in[13];
    const float* We2   = (const float*)d_in[14];
    const float* att2  = (const float*)d_in[15];
    const float* bias2 = (const float*)d_in[16];
    const float* w_ln1 = (const float*)d_in[17];
    const float* w_ln3 = (const float*)d_in[18];
    const float* W_out = (const float*)d_in[19];
    float* out = (float*)d_out;

    const int* srcp = ei;
    const int* dstp = ei + NE;

    float* xl1  = (float*)sym(g_xl1);
    float* xr1  = (float*)sym(g_xr1);
    float* acc1 = (float*)sym(g_acc1);
    float* xl2  = (float*)sym(g_xl2);
    float* xr2  = (float*)sym(g_xr2);
    float* acc2 = (float*)sym(g_acc2);
    float* expv = (float*)sym(g_expv);
    float* den1 = (float*)sym(g_den1);
    float* den2 = (float*)sym(g_den2);
    float* cnt  = (float*)sym(g_cnt);
    float* latt = (float*)sym(g_lattr);

    zero_k<<<2048, 256>>>(acc1, NN * D1);
    zero_k<<<1024, 256>>>(acc2, NN * D2);
    zero_k<<<64, 256>>>(den1, NN * H);
    zero_k<<<64, 256>>>(den2, NN * H);
    zero_k<<<64, 256>>>(cnt, NN);
    zero_k<<<64, 256>>>(latt, NN);

    edge_count_k<<<(NE + 255) / 256, 256>>>(dstp, eattr, cnt, latt, NE);
    loop_attr_k<<<(NN + 255) / 256, 256>>>(latt, cnt, NN);

    // --- layer 1 node transforms (tensor core, 3xTF32): M=30000, N=512, K=128 ---
    dim3 g1(D1 / 64, (NN + 127) / 128);
    gemm_tc_k<<<g1, 256>>>(x, Wl1, bl1, xl1, NN, D1, D2);
    gemm_tc_k<<<g1, 256>>>(x, Wr1, br1, xr1, NN, D1, D2);

    int nwarp = NE2 * H;
    int nblk = (nwarp * 32 + 255) / 256;
    logits_k<<<nblk, 256>>>(srcp, dstp, eattr, latt, xl1, xr1, We1, att1, expv, den1, NE, NN, C1);
    aggregate_k<<<nblk, 256>>>(srcp, dstp, xl1, expv, den1, acc1, NE, NN, C1);

    postact_rms_k<<<NN, 256>>>(acc1, bias1, w_ln1, acc1, D1, 1);

    // --- layer 2 node transforms: M=30000, N=128, K=512 ---
    dim3 g2(D2 / 64, (NN + 127) / 128);
    gemm_tc_k<<<g2, 256>>>(acc1, Wl2, bl2, xl2, NN, D2, D1);
    gemm_tc_k<<<g2, 256>>>(acc1, Wr2, br2, xr2, NN, D2, D1);

    logits_k<<<nblk, 256>>>(srcp, dstp, eattr, latt, xl2, xr2, We2, att2, expv, den2, NE, NN, C2);
    aggregate_k<<<nblk, 256>>>(srcp, dstp, xl2, expv, den2, acc2, NE, NN, C2);

    postact_rms_k<<<NN, 256>>>(acc2, bias2, w_ln3, acc2, D2, 0);

    int ntot = NN * NCLS;
    out_gemm_k<<<(ntot + 255) / 256, 256, NCLS * D2 * sizeof(float)>>>(acc2, W_out, out, NN, D2, NCLS);
}

// round 3
// speedup vs baseline: 1.4140x; 1.0307x over previous
#include <cuda_runtime.h>
#include <cuda_bf16.h>

#define NN 30000
#define NE 240000
#define NE2 (NE + NN)
#define D1 512
#define D2 128
#define H 2
#define C1 256
#define C2 64
#define NCLS 20
#define EPS 1e-5f
#define NEG 0.2f

// ---------------- scratch (device globals; no allocations) ----------------
__device__ float g_xl1[(size_t)NN * D1];
__device__ float g_xr1[(size_t)NN * D1];
__device__ float g_acc1[(size_t)NN * D1];
__device__ float g_xl2[(size_t)NN * D2];
__device__ float g_xr2[(size_t)NN * D2];
__device__ float g_acc2[(size_t)NN * D2];
__device__ float g_den1[(size_t)NN * H];
__device__ float g_den2[(size_t)NN * H];
__device__ float g_cnt[NN];
__device__ float g_lattr[NN];

// ---------------- consolidated zero ----------------
#define ZT ((size_t)NN * D1 + (size_t)NN * D2 + 2 * NN * H + 2 * NN)
__global__ void zero_all_k(float* a1, float* a2, float* d1, float* d2, float* c, float* l) {
    size_t i = (size_t)blockIdx.x * blockDim.x + threadIdx.x;
    size_t stride = (size_t)gridDim.x * blockDim.x;
    const size_t s1 = (size_t)NN * D1;
    const size_t s2 = s1 + (size_t)NN * D2;
    const size_t s3 = s2 + NN * H;
    const size_t s4 = s3 + NN * H;
    const size_t s5 = s4 + NN;
    for (; i < ZT; i += stride) {
        if (i < s1) a1[i] = 0.f;
        else if (i < s2) a2[i - s1] = 0.f;
        else if (i < s3) d1[i - s2] = 0.f;
        else if (i < s4) d2[i - s3] = 0.f;
        else if (i < s5) c[i - s4] = 0.f;
        else l[i - s5] = 0.f;
    }
}

__global__ void edge_count_k(const int* __restrict__ dst, const float* __restrict__ eattr,
                             float* __restrict__ cnt, float* __restrict__ asum, int E) {
    int e = blockIdx.x * blockDim.x + threadIdx.x;
    if (e < E) {
        int d = dst[e];
        atomicAdd(&cnt[d], 1.f);
        atomicAdd(&asum[d], eattr[e]);
    }
}

__global__ void loop_attr_k(float* __restrict__ asum, const float* __restrict__ cnt, int n) {
    int i = blockIdx.x * blockDim.x + threadIdx.x;
    if (i < n) asum[i] = asum[i] / fmaxf(cnt[i], 1.f);
}

// ---------------- TF32 helpers ----------------
__device__ __forceinline__ unsigned f2tf32(float f) {
    unsigned r;
    asm("cvt.rna.tf32.f32 %0, %1;" : "=r"(r) : "f"(f));
    return r;
}
__device__ __forceinline__ void split_tf32(float f, unsigned& hi, unsigned& lo) {
    hi = f2tf32(f);
    lo = f2tf32(f - __uint_as_float(hi));
}
__device__ __forceinline__ void mma_tf32(float* c, const unsigned* a, const unsigned* b) {
    asm volatile(
        "mma.sync.aligned.m16n8k8.row.col.f32.tf32.tf32.f32 "
        "{%0,%1,%2,%3}, {%4,%5,%6,%7}, {%8,%9}, {%0,%1,%2,%3};\n"
        : "+f"(c[0]), "+f"(c[1]), "+f"(c[2]), "+f"(c[3])
        : "r"(a[0]), "r"(a[1]), "r"(a[2]), "r"(a[3]), "r"(b[0]), "r"(b[1]));
}

// ---------------- TC GEMM: C[M,N] = A[M,K] @ B[N,K]^T + bias[N] ----------------
__global__ __launch_bounds__(256) void gemm_tc_k(
    const float* __restrict__ A, const float* __restrict__ B,
    const float* __restrict__ bias, float* __restrict__ C,
    int M, int N, int K) {
    __shared__ float As[128][20];
    __shared__ float Bs[64][20];

    const int tid = threadIdx.x;
    const int lane = tid & 31;
    const int warp = tid >> 5;
    const int wm = warp >> 1;
    const int wn = warp & 1;
    const int groupID = lane >> 2;
    const int tg = lane & 3;

    const int bm = blockIdx.y * 128;
    const int bn = blockIdx.x * 64;

    float acc[2][4][4] = {};

    for (int k0 = 0; k0 < K; k0 += 16) {
#pragma unroll
        for (int i = 0; i < 2; i++) {
            int idx = tid + i * 256;
            int m = idx >> 2;
            int k4 = idx & 3;
            int gm = bm + m;
            if (gm >= M) gm = M - 1;
            float4 v = *(const float4*)&A[(size_t)gm * K + k0 + k4 * 4];
            As[m][k4 * 4 + 0] = v.x;
            As[m][k4 * 4 + 1] = v.y;
            As[m][k4 * 4 + 2] = v.z;
            As[m][k4 * 4 + 3] = v.w;
        }
        {
            int n = tid >> 2;
            int k4 = tid & 3;
            float4 v = *(const float4*)&B[(size_t)(bn + n) * K + k0 + k4 * 4];
            Bs[n][k4 * 4 + 0] = v.x;
            Bs[n][k4 * 4 + 1] = v.y;
            Bs[n][k4 * 4 + 2] = v.z;
            Bs[n][k4 * 4 + 3] = v.w;
        }
        __syncthreads();

#pragma unroll
        for (int ks = 0; ks < 16; ks += 8) {
            unsigned ahi[2][4], alo[2][4], bhi[4][2], blo[4][2];
#pragma unroll
            for (int mt = 0; mt < 2; mt++) {
                int r = wm * 32 + mt * 16 + groupID;
                split_tf32(As[r][ks + tg], ahi[mt][0], alo[mt][0]);
                split_tf32(As[r + 8][ks + tg], ahi[mt][1], alo[mt][1]);
                split_tf32(As[r][ks + tg + 4], ahi[mt][2], alo[mt][2]);
                split_tf32(As[r + 8][ks + tg + 4], ahi[mt][3], alo[mt][3]);
            }
#pragma unroll
            for (int nt = 0; nt < 4; nt++) {
                int n = wn * 32 + nt * 8 + groupID;
                split_tf32(Bs[n][ks + tg], bhi[nt][0], blo[nt][0]);
                split_tf32(Bs[n][ks + tg + 4], bhi[nt][1], blo[nt][1]);
            }
#pragma unroll
            for (int mt = 0; mt < 2; mt++)
#pragma unroll
                for (int nt = 0; nt < 4; nt++) {
                    mma_tf32(acc[mt][nt], ahi[mt], bhi[nt]);
                    mma_tf32(acc[mt][nt], alo[mt], bhi[nt]);
                    mma_tf32(acc[mt][nt], ahi[mt], blo[nt]);
                }
        }
        __syncthreads();
    }

#pragma unroll
    for (int mt = 0; mt < 2; mt++) {
        int row0 = bm + wm * 32 + mt * 16 + groupID;
#pragma unroll
        for (int nt = 0; nt < 4; nt++) {
            int col0 = bn + wn * 32 + nt * 8 + tg * 2;
            float b0 = bias[col0], b1 = bias[col0 + 1];
            if (row0 < M) {
                C[(size_t)row0 * N + col0] = acc[mt][nt][0] + b0;
                C[(size_t)row0 * N + col0 + 1] = acc[mt][nt][1] + b1;
            }
            if (row0 + 8 < M) {
                C[(size_t)(row0 + 8) * N + col0] = acc[mt][nt][2] + b0;
                C[(size_t)(row0 + 8) * N + col0 + 1] = acc[mt][nt][3] + b1;
            }
        }
    }
}

// ---------------- FUSED edge pass: logit + exp + denom + weighted scatter ----------------
// warp per (edge, head). acc[d] += p * xl[s]; denom[d,h] += p. Normalization deferred.
template <int C>
__global__ void edge_fused_k(const int* __restrict__ src, const int* __restrict__ dst,
                             const float* __restrict__ eattr, const float* __restrict__ lattr,
                             const float* __restrict__ xl, const float* __restrict__ xr,
                             const float* __restrict__ We, const float* __restrict__ att,
                             float* __restrict__ acc, float* __restrict__ denom,
                             int E, int N) {
    int gw = (blockIdx.x * blockDim.x + threadIdx.x) >> 5;
    int lane = threadIdx.x & 31;
    int total = (E + N) * H;
    if (gw >= total) return;
    int h = gw & (H - 1);
    int e = gw >> 1;
    int s, d;
    float ea;
    if (e < E) { s = src[e]; d = dst[e]; ea = eattr[e]; }
    else       { s = d = e - E; ea = lattr[s]; }

    constexpr int Dd = H * C;
    const float* xls = xl + (size_t)s * Dd + h * C;
    const float* xrd = xr + (size_t)d * Dd + h * C;
    const float* Weh = We + h * C;
    const float* ath = att + h * C;

    float lg = 0.f;
    if (C == 256) {
        float4 xv[2];
#pragma unroll
        for (int it = 0; it < 2; it++) {
            int c = (lane + it * 32) * 4;
            float4 a = *(const float4*)&xls[c];
            float4 b = *(const float4*)&xrd[c];
            float4 w = *(const float4*)&Weh[c];
            float4 t = *(const float4*)&ath[c];
            xv[it] = a;
            float v0 = a.x + b.x + ea * w.x; v0 = v0 > 0.f ? v0 : NEG * v0;
            float v1 = a.y + b.y + ea * w.y; v1 = v1 > 0.f ? v1 : NEG * v1;
            float v2 = a.z + b.z + ea * w.z; v2 = v2 > 0.f ? v2 : NEG * v2;
            float v3 = a.w + b.w + ea * w.w; v3 = v3 > 0.f ? v3 : NEG * v3;
            lg += v0 * t.x + v1 * t.y + v2 * t.z + v3 * t.w;
        }
#pragma unroll
        for (int o = 16; o > 0; o >>= 1) lg += __shfl_xor_sync(0xffffffffu, lg, o);
        float p = __expf(lg);
        if (lane == 0) atomicAdd(&denom[(size_t)d * H + h], p);
        float* od = acc + (size_t)d * Dd + h * C;
#pragma unroll
        for (int it = 0; it < 2; it++) {
            int c = (lane + it * 32) * 4;
            atomicAdd(&od[c + 0], p * xv[it].x);
            atomicAdd(&od[c + 1], p * xv[it].y);
            atomicAdd(&od[c + 2], p * xv[it].z);
            atomicAdd(&od[c + 3], p * xv[it].w);
        }
    } else {  // C == 64
        int c = lane * 2;
        float2 a = *(const float2*)&xls[c];
        float2 b = *(const float2*)&xrd[c];
        float2 w = *(const float2*)&Weh[c];
        float2 t = *(const float2*)&ath[c];
        float v0 = a.x + b.x + ea * w.x; v0 = v0 > 0.f ? v0 : NEG * v0;
        float v1 = a.y + b.y + ea * w.y; v1 = v1 > 0.f ? v1 : NEG * v1;
        lg = v0 * t.x + v1 * t.y;
#pragma unroll
        for (int o = 16; o > 0; o >>= 1) lg += __shfl_xor_sync(0xffffffffu, lg, o);
        float p = __expf(lg);
        if (lane == 0) atomicAdd(&denom[(size_t)d * H + h], p);
        float* od = acc + (size_t)d * Dd + h * C;
        atomicAdd(&od[c + 0], p * a.x);
        atomicAdd(&od[c + 1], p * a.y);
    }
}

// ---------------- normalize + bias + (silu) + rmsnorm, one block per node ----------------
__global__ void postact_rms_k(const float* __restrict__ acc, const float* __restrict__ denom,
                              const float* __restrict__ bias,
                              const float* __restrict__ w, float* __restrict__ out,
                              int D, int C, int do_silu) {
    int n = blockIdx.x;
    float vals[2];
    float ss = 0.f;
    int nv = 0;
    float dinv[H];
#pragma unroll
    for (int h = 0; h < H; h++) dinv[h] = 1.f / denom[(size_t)n * H + h];
    for (int j = threadIdx.x; j < D; j += blockDim.x) {
        float v = acc[(size_t)n * D + j] * dinv[j / C] + bias[j];
        if (do_silu) v = v / (1.f + __expf(-v));
        vals[nv++] = v;
        ss += v * v;
    }
    __shared__ float red[32];
    int lane = threadIdx.x & 31, wid = threadIdx.x >> 5;
#pragma unroll
    for (int o = 16; o > 0; o >>= 1) ss += __shfl_down_sync(0xffffffffu, ss, o);
    if (lane == 0) red[wid] = ss;
    __syncthreads();
    if (wid == 0) {
        float s2 = (lane < (blockDim.x >> 5)) ? red[lane] : 0.f;
#pragma unroll
        for (int o = 16; o > 0; o >>= 1) s2 += __shfl_down_sync(0xffffffffu, s2, o);
        if (lane == 0) red[0] = s2;
    }
    __syncthreads();
    float inv = rsqrtf(red[0] / (float)D + EPS);
    nv = 0;
    for (int j = threadIdx.x; j < D; j += blockDim.x)
        out[(size_t)n * D + j] = vals[nv++] * inv * w[j];
}

// ---------------- classifier ----------------
__global__ void out_gemm_k(const float* __restrict__ h, const float* __restrict__ W,
                           float* __restrict__ out, int N, int K, int Cn) {
    extern __shared__ float Ws[];
    for (int i = threadIdx.x; i < Cn * K; i += blockDim.x) Ws[i] = W[i];
    __syncthreads();
    int idx = blockIdx.x * blockDim.x + threadIdx.x;
    if (idx >= N * Cn) return;
    int n = idx / Cn, c = idx % Cn;
    const float* hr = h + (size_t)n * K;
    const float* wr = Ws + c * K;
    float s = 0.f;
#pragma unroll 8
    for (int k = 0; k < K; k++) s += hr[k] * wr[k];
    out[idx] = s;
}

// ---------------- launch ----------------
static void* sym(const void* s) {
    void* p = nullptr;
    cudaGetSymbolAddress(&p, s);
    return p;
}

extern "C" void kernel_launch(void* const* d_in, const int* in_sizes, int n_in,
                              void* d_out, int out_size) {
    const float* x     = (const float*)d_in[0];
    const int*   ei    = (const int*)d_in[1];
    const float* eattr = (const float*)d_in[2];
    const float* Wl1   = (const float*)d_in[3];
    const float* bl1   = (const float*)d_in[4];
    const float* Wr1   = (const float*)d_in[5];
    const float* br1   = (const float*)d_in[6];
    const float* We1   = (const float*)d_in[7];
    const float* att1  = (const float*)d_in[8];
    const float* bias1 = (const float*)d_in[9];
    const float* Wl2   = (const float*)d_in[10];
    const float* bl2   = (const float*)d_in[11];
    const float* Wr2   = (const float*)d_in[12];
    const float* br2   = (const float*)d_in[13];
    const float* We2   = (const float*)d_in[14];
    const float* att2  = (const float*)d_in[15];
    const float* bias2 = (const float*)d_in[16];
    const float* w_ln1 = (const float*)d_in[17];
    const float* w_ln3 = (const float*)d_in[18];
    const float* W_out = (const float*)d_in[19];
    float* out = (float*)d_out;

    const int* srcp = ei;
    const int* dstp = ei + NE;

    float* xl1  = (float*)sym(g_xl1);
    float* xr1  = (float*)sym(g_xr1);
    float* acc1 = (float*)sym(g_acc1);
    float* xl2  = (float*)sym(g_xl2);
    float* xr2  = (float*)sym(g_xr2);
    float* acc2 = (float*)sym(g_acc2);
    float* den1 = (float*)sym(g_den1);
    float* den2 = (float*)sym(g_den2);
    float* cnt  = (float*)sym(g_cnt);
    float* latt = (float*)sym(g_lattr);

    // launch 0: zero everything
    zero_all_k<<<4096, 256>>>(acc1, acc2, den1, den2, cnt, latt);
    // 1-2: self-loop attr
    edge_count_k<<<(NE + 255) / 256, 256>>>(dstp, eattr, cnt, latt, NE);
    loop_attr_k<<<(NN + 255) / 256, 256>>>(latt, cnt, NN);
    // 3-4: layer 1 transforms
    dim3 g1(D1 / 64, (NN + 127) / 128);
    gemm_tc_k<<<g1, 256>>>(x, Wl1, bl1, xl1, NN, D1, D2);
    gemm_tc_k<<<g1, 256>>>(x, Wr1, br1, xr1, NN, D1, D2);
    // 5: fused edge pass layer 1 (ncu -s 5 lands here)
    int nwarp = NE2 * H;
    int nblk = (nwarp * 32 + 255) / 256;
    edge_fused_k<C1><<<nblk, 256>>>(srcp, dstp, eattr, latt, xl1, xr1, We1, att1, acc1, den1, NE, NN);
    // 6: normalize + silu + rmsnorm
    postact_rms_k<<<NN, 256>>>(acc1, den1, bias1, w_ln1, acc1, D1, C1, 1);
    // 7-8: layer 2 transforms
    dim3 g2(D2 / 64, (NN + 127) / 128);
    gemm_tc_k<<<g2, 256>>>(acc1, Wl2, bl2, xl2, NN, D2, D1);
    gemm_tc_k<<<g2, 256>>>(acc1, Wr2, br2, xr2, NN, D2, D1);
    // 9: fused edge pass layer 2
    edge_fused_k<C2><<<nblk, 256>>>(srcp, dstp, eattr, latt, xl2, xr2, We2, att2, acc2, den2, NE, NN);
    // 10: normalize + rmsnorm
    postact_rms_k<<<NN, 256>>>(acc2, den2, bias2, w_ln3, acc2, D2, C2, 0);
    // 11: classifier
    int ntot = NN * NCLS;
    out_gemm_k<<<(ntot + 255) / 256, 256, NCLS * D2 * sizeof(float)>>>(acc2, W_out, out, NN, D2, NCLS);
}

// round 4
// speedup vs baseline: 1.8610x; 1.3161x over previous
#include <cuda_runtime.h>
#include <cuda_bf16.h>

#define NN 30000
#define NE 240000
#define D1 512
#define D2 128
#define H 2
#define C1 256
#define C2 64
#define NCLS 20
#define EPS 1e-5f
#define NEG 0.2f

// ---------------- scratch (device globals; no allocations) ----------------
__device__ float g_xlr1[(size_t)NN * 2 * D1];  // [node][xl(512) | xr(512)]
__device__ float g_acc1[(size_t)NN * D1];
__device__ float g_xlr2[(size_t)NN * 2 * D2];  // [node][xl(128) | xr(128)]
__device__ float g_acc2[(size_t)NN * D2];
__device__ int g_deg[NN];
__device__ int g_off[NN + 1];
__device__ int g_cursor[NN];
__device__ int g_eid[NE];

// ---------------- CSR build ----------------
__global__ void zero_deg_k(int* deg) {
    int i = blockIdx.x * blockDim.x + threadIdx.x;
    if (i < NN) deg[i] = 0;
}
__global__ void hist_k(const int* __restrict__ dst, int* __restrict__ deg) {
    int e = blockIdx.x * blockDim.x + threadIdx.x;
    if (e < NE) atomicAdd(&deg[dst[e]], 1);
}
__global__ __launch_bounds__(1024) void scan_k(const int* __restrict__ deg,
                                               int* __restrict__ off, int* __restrict__ cursor) {
    __shared__ int partial[1024];
    int t = threadIdx.x;
    const int CH = (NN + 1023) / 1024;  // 30
    int base = t * CH;
    int s = 0;
    for (int i = 0; i < CH; i++) {
        int idx = base + i;
        if (idx < NN) s += deg[idx];
    }
    partial[t] = s;
    __syncthreads();
    for (int o = 1; o < 1024; o <<= 1) {
        int v = (t >= o) ? partial[t - o] : 0;
        __syncthreads();
        partial[t] += v;
        __syncthreads();
    }
    int run = (t == 0) ? 0 : partial[t - 1];
    for (int i = 0; i < CH; i++) {
        int idx = base + i;
        if (idx < NN) {
            off[idx] = run;
            cursor[idx] = run;
            run += deg[idx];
        }
    }
    if (t == 1023) off[NN] = partial[1023];
}
__global__ void scatter_k(const int* __restrict__ dst, int* __restrict__ cursor,
                          int* __restrict__ eid) {
    int e = blockIdx.x * blockDim.x + threadIdx.x;
    if (e < NE) {
        int pos = atomicAdd(&cursor[dst[e]], 1);
        eid[pos] = e;
    }
}

// ---------------- TF32 helpers ----------------
__device__ __forceinline__ unsigned f2tf32(float f) {
    unsigned r;
    asm("cvt.rna.tf32.f32 %0, %1;" : "=r"(r) : "f"(f));
    return r;
}
__device__ __forceinline__ void mma_tf32(float* c, const unsigned* a, const unsigned* b) {
    asm volatile(
        "mma.sync.aligned.m16n8k8.row.col.f32.tf32.tf32.f32 "
        "{%0,%1,%2,%3}, {%4,%5,%6,%7}, {%8,%9}, {%0,%1,%2,%3};\n"
        : "+f"(c[0]), "+f"(c[1]), "+f"(c[2]), "+f"(c[3])
        : "r"(a[0]), "r"(a[1]), "r"(a[2]), "r"(a[3]), "r"(b[0]), "r"(b[1]));
}

// ---------------- dual-B TC GEMM with split-at-load ----------------
// C[M, 2*Nhalf]: cols [0,Nhalf) = A @ B0^T + bias0 ; cols [Nhalf,2Nhalf) = A @ B1^T + bias1
// block tile 128x64, 256 threads, BK=16, 3xTF32.
__global__ __launch_bounds__(256) void gemm_tc2_k(
    const float* __restrict__ A,
    const float* __restrict__ B0, const float* __restrict__ B1,
    const float* __restrict__ bias0, const float* __restrict__ bias1,
    float* __restrict__ C, int M, int Nhalf, int K) {
    const int N = 2 * Nhalf;
    __shared__ unsigned AsH[128][20], AsL[128][20];
    __shared__ unsigned BsH[64][20], BsL[64][20];

    const int tid = threadIdx.x;
    const int lane = tid & 31;
    const int warp = tid >> 5;
    const int wm = warp >> 1;
    const int wn = warp & 1;
    const int groupID = lane >> 2;
    const int tg = lane & 3;

    const int bm = blockIdx.y * 128;
    const int bn = blockIdx.x * 64;

    float acc[2][4][4] = {};

    for (int k0 = 0; k0 < K; k0 += 16) {
#pragma unroll
        for (int i = 0; i < 2; i++) {
            int idx = tid + i * 256;
            int m = idx >> 2;
            int k4 = idx & 3;
            int gm = bm + m;
            if (gm >= M) gm = M - 1;
            float4 v = *(const float4*)&A[(size_t)gm * K + k0 + k4 * 4];
            float fv[4] = {v.x, v.y, v.z, v.w};
#pragma unroll
            for (int j = 0; j < 4; j++) {
                unsigned hi = f2tf32(fv[j]);
                AsH[m][k4 * 4 + j] = hi;
                AsL[m][k4 * 4 + j] = f2tf32(fv[j] - __uint_as_float(hi));
            }
        }
        {
            int n = tid >> 2;
            int k4 = tid & 3;
            int gn = bn + n;
            const float* Bp = (gn < Nhalf) ? B0 : B1;
            int col = (gn < Nhalf) ? gn : gn - Nhalf;
            float4 v = *(const float4*)&Bp[(size_t)col * K + k0 + k4 * 4];
            float fv[4] = {v.x, v.y, v.z, v.w};
#pragma unroll
            for (int j = 0; j < 4; j++) {
                unsigned hi = f2tf32(fv[j]);
                BsH[n][k4 * 4 + j] = hi;
                BsL[n][k4 * 4 + j] = f2tf32(fv[j] - __uint_as_float(hi));
            }
        }
        __syncthreads();

#pragma unroll
        for (int ks = 0; ks < 16; ks += 8) {
            unsigned ahi[2][4], alo[2][4], bhi[4][2], blo[4][2];
#pragma unroll
            for (int mt = 0; mt < 2; mt++) {
                int r = wm * 32 + mt * 16 + groupID;
                ahi[mt][0] = AsH[r][ks + tg];     alo[mt][0] = AsL[r][ks + tg];
                ahi[mt][1] = AsH[r + 8][ks + tg]; alo[mt][1] = AsL[r + 8][ks + tg];
                ahi[mt][2] = AsH[r][ks + tg + 4];     alo[mt][2] = AsL[r][ks + tg + 4];
                ahi[mt][3] = AsH[r + 8][ks + tg + 4]; alo[mt][3] = AsL[r + 8][ks + tg + 4];
            }
#pragma unroll
            for (int nt = 0; nt < 4; nt++) {
                int n = wn * 32 + nt * 8 + groupID;
                bhi[nt][0] = BsH[n][ks + tg];     blo[nt][0] = BsL[n][ks + tg];
                bhi[nt][1] = BsH[n][ks + tg + 4]; blo[nt][1] = BsL[n][ks + tg + 4];
            }
#pragma unroll
            for (int mt = 0; mt < 2; mt++)
#pragma unroll
                for (int nt = 0; nt < 4; nt++) {
                    mma_tf32(acc[mt][nt], ahi[mt], bhi[nt]);
                    mma_tf32(acc[mt][nt], alo[mt], bhi[nt]);
                    mma_tf32(acc[mt][nt], ahi[mt], blo[nt]);
                }
        }
        __syncthreads();
    }

#pragma unroll
    for (int mt = 0; mt < 2; mt++) {
        int row0 = bm + wm * 32 + mt * 16 + groupID;
#pragma unroll
        for (int nt = 0; nt < 4; nt++) {
            int col0 = bn + wn * 32 + nt * 8 + tg * 2;
            float b0 = (col0 < Nhalf) ? bias0[col0] : bias1[col0 - Nhalf];
            float b1 = (col0 + 1 < Nhalf) ? bias0[col0 + 1] : bias1[col0 + 1 - Nhalf];
            if (row0 < M) {
                C[(size_t)row0 * N + col0] = acc[mt][nt][0] + b0;
                C[(size_t)row0 * N + col0 + 1] = acc[mt][nt][1] + b1;
            }
            if (row0 + 8 < M) {
                C[(size_t)(row0 + 8) * N + col0] = acc[mt][nt][2] + b0;
                C[(size_t)(row0 + 8) * N + col0 + 1] = acc[mt][nt][3] + b1;
            }
        }
    }
}

// ---------------- CSR edge pass, layer 1 (C=256): warp per (dst, head) ----------------
__global__ __launch_bounds__(256) void gat_edge1_k(
    const int* __restrict__ srcp, const float* __restrict__ eattr,
    const int* __restrict__ off, const int* __restrict__ eid,
    const float* __restrict__ xlr, const float* __restrict__ We,
    const float* __restrict__ att, float* __restrict__ outv) {
    int gw = (blockIdx.x * 256 + threadIdx.x) >> 5;
    int lane = threadIdx.x & 31;
    if (gw >= NN * H) return;
    int h = gw & 1;
    int d = gw >> 1;
    const int STR = 2 * D1;  // 1024
    const int c0 = lane * 4, c1 = 128 + lane * 4;

    const float* xrd = xlr + (size_t)d * STR + D1 + h * C1;
    float4 xr_a = *(const float4*)&xrd[c0];
    float4 xr_b = *(const float4*)&xrd[c1];
    const float* Weh = We + h * C1;
    float4 w_a = *(const float4*)&Weh[c0];
    float4 w_b = *(const float4*)&Weh[c1];
    const float* ath = att + h * C1;
    float4 t_a = *(const float4*)&ath[c0];
    float4 t_b = *(const float4*)&ath[c1];

    float4 acc_a = {0, 0, 0, 0}, acc_b = {0, 0, 0, 0};
    float denom = 0.f, easum = 0.f;
    int i0 = off[d], i1 = off[d + 1];

    for (int i = i0; i <= i1; i++) {
        int s;
        float ea;
        if (i < i1) {
            int e = eid[i];
            s = srcp[e];
            ea = eattr[e];
            easum += ea;
        } else {  // self loop
            s = d;
            ea = easum / fmaxf((float)(i1 - i0), 1.f);
        }
        const float* xls = xlr + (size_t)s * STR + h * C1;
        float4 a_a = *(const float4*)&xls[c0];
        float4 a_b = *(const float4*)&xls[c1];
        float v, lg = 0.f;
        v = a_a.x + xr_a.x + ea * w_a.x; v = v > 0.f ? v : NEG * v; lg += v * t_a.x;
        v = a_a.y + xr_a.y + ea * w_a.y; v = v > 0.f ? v : NEG * v; lg += v * t_a.y;
        v = a_a.z + xr_a.z + ea * w_a.z; v = v > 0.f ? v : NEG * v; lg += v * t_a.z;
        v = a_a.w + xr_a.w + ea * w_a.w; v = v > 0.f ? v : NEG * v; lg += v * t_a.w;
        v = a_b.x + xr_b.x + ea * w_b.x; v = v > 0.f ? v : NEG * v; lg += v * t_b.x;
        v = a_b.y + xr_b.y + ea * w_b.y; v = v > 0.f ? v : NEG * v; lg += v * t_b.y;
        v = a_b.z + xr_b.z + ea * w_b.z; v = v > 0.f ? v : NEG * v; lg += v * t_b.z;
        v = a_b.w + xr_b.w + ea * w_b.w; v = v > 0.f ? v : NEG * v; lg += v * t_b.w;
#pragma unroll
        for (int o = 16; o > 0; o >>= 1) lg += __shfl_xor_sync(0xffffffffu, lg, o);
        float p = __expf(lg);
        denom += p;
        acc_a.x += p * a_a.x; acc_a.y += p * a_a.y; acc_a.z += p * a_a.z; acc_a.w += p * a_a.w;
        acc_b.x += p * a_b.x; acc_b.y += p * a_b.y; acc_b.z += p * a_b.z; acc_b.w += p * a_b.w;
    }
    float inv = 1.f / denom;
    float* od = outv + (size_t)d * D1 + h * C1;
    float4 o_a = {acc_a.x * inv, acc_a.y * inv, acc_a.z * inv, acc_a.w * inv};
    float4 o_b = {acc_b.x * inv, acc_b.y * inv, acc_b.z * inv, acc_b.w * inv};
    *(float4*)&od[c0] = o_a;
    *(float4*)&od[c1] = o_b;
}

// ---------------- CSR edge pass, layer 2 (C=64): warp per dst, both heads ----------------
__global__ __launch_bounds__(256) void gat_edge2_k(
    const int* __restrict__ srcp, const float* __restrict__ eattr,
    const int* __restrict__ off, const int* __restrict__ eid,
    const float* __restrict__ xlr, const float* __restrict__ We,
    const float* __restrict__ att, float* __restrict__ outv) {
    int gw = (blockIdx.x * 256 + threadIdx.x) >> 5;
    int lane = threadIdx.x & 31;
    if (gw >= NN) return;
    int d = gw;
    const int STR = 2 * D2;  // 256
    int h = lane >> 4;               // lanes 0-15: head0, 16-31: head1
    int cl = (lane & 15) * 4;        // column within head
    int gc = h * C2 + cl;            // column within xl/xr block (0..127)

    const float* xrd = xlr + (size_t)d * STR + D2;
    float4 xr_v = *(const float4*)&xrd[gc];
    float4 w_v = *(const float4*)&We[gc];
    float4 t_v = *(const float4*)&att[gc];

    float4 acc = {0, 0, 0, 0};
    float denom = 0.f, easum = 0.f;
    int i0 = off[d], i1 = off[d + 1];

    for (int i = i0; i <= i1; i++) {
        int s;
        float ea;
        if (i < i1) {
            int e = eid[i];
            s = srcp[e];
            ea = eattr[e];
            easum += ea;
        } else {
            s = d;
            ea = easum / fmaxf((float)(i1 - i0), 1.f);
        }
        const float* xls = xlr + (size_t)s * STR;
        float4 a = *(const float4*)&xls[gc];
        float v, lg = 0.f;
        v = a.x + xr_v.x + ea * w_v.x; v = v > 0.f ? v : NEG * v; lg += v * t_v.x;
        v = a.y + xr_v.y + ea * w_v.y; v = v > 0.f ? v : NEG * v; lg += v * t_v.y;
        v = a.z + xr_v.z + ea * w_v.z; v = v > 0.f ? v : NEG * v; lg += v * t_v.z;
        v = a.w + xr_v.w + ea * w_v.w; v = v > 0.f ? v : NEG * v; lg += v * t_v.w;
#pragma unroll
        for (int o = 8; o > 0; o >>= 1) lg += __shfl_xor_sync(0xffffffffu, lg, o);
        float p = __expf(lg);
        denom += p;
        acc.x += p * a.x; acc.y += p * a.y; acc.z += p * a.z; acc.w += p * a.w;
    }
    float inv = 1.f / denom;
    float* od = outv + (size_t)d * D2 + gc;
    float4 o = {acc.x * inv, acc.y * inv, acc.z * inv, acc.w * inv};
    *(float4*)&od[0] = o;
}

// ---------------- bias + (silu) + rmsnorm ----------------
__global__ void postact_rms_k(const float* __restrict__ acc, const float* __restrict__ bias,
                              const float* __restrict__ w, float* __restrict__ out,
                              int D, int do_silu) {
    int n = blockIdx.x;
    float vals[2];
    float ss = 0.f;
    int nv = 0;
    for (int j = threadIdx.x; j < D; j += blockDim.x) {
        float v = acc[(size_t)n * D + j] + bias[j];
        if (do_silu) v = v / (1.f + __expf(-v));
        vals[nv++] = v;
        ss += v * v;
    }
    __shared__ float red[32];
    int lane = threadIdx.x & 31, wid = threadIdx.x >> 5;
#pragma unroll
    for (int o = 16; o > 0; o >>= 1) ss += __shfl_down_sync(0xffffffffu, ss, o);
    if (lane == 0) red[wid] = ss;
    __syncthreads();
    if (wid == 0) {
        float s2 = (lane < (blockDim.x >> 5)) ? red[lane] : 0.f;
#pragma unroll
        for (int o = 16; o > 0; o >>= 1) s2 += __shfl_down_sync(0xffffffffu, s2, o);
        if (lane == 0) red[0] = s2;
    }
    __syncthreads();
    float inv = rsqrtf(red[0] / (float)D + EPS);
    nv = 0;
    for (int j = threadIdx.x; j < D; j += blockDim.x)
        out[(size_t)n * D + j] = vals[nv++] * inv * w[j];
}

// ---------------- classifier ----------------
__global__ void out_gemm_k(const float* __restrict__ h, const float* __restrict__ W,
                           float* __restrict__ out, int N, int K, int Cn) {
    extern __shared__ float Ws[];
    for (int i = threadIdx.x; i < Cn * K; i += blockDim.x) Ws[i] = W[i];
    __syncthreads();
    int idx = blockIdx.x * blockDim.x + threadIdx.x;
    if (idx >= N * Cn) return;
    int n = idx / Cn, c = idx % Cn;
    const float* hr = h + (size_t)n * K;
    const float* wr = Ws + c * K;
    float s = 0.f;
#pragma unroll 8
    for (int k = 0; k < K; k++) s += hr[k] * wr[k];
    out[idx] = s;
}

// ---------------- launch ----------------
static void* sym(const void* s) {
    void* p = nullptr;
    cudaGetSymbolAddress(&p, s);
    return p;
}

extern "C" void kernel_launch(void* const* d_in, const int* in_sizes, int n_in,
                              void* d_out, int out_size) {
    const float* x     = (const float*)d_in[0];
    const int*   ei    = (const int*)d_in[1];
    const float* eattr = (const float*)d_in[2];
    const float* Wl1   = (const float*)d_in[3];
    const float* bl1   = (const float*)d_in[4];
    const float* Wr1   = (const float*)d_in[5];
    const float* br1   = (const float*)d_in[6];
    const float* We1   = (const float*)d_in[7];
    const float* att1  = (const float*)d_in[8];
    const float* bias1 = (const float*)d_in[9];
    const float* Wl2   = (const float*)d_in[10];
    const float* bl2   = (const float*)d_in[11];
    const float* Wr2   = (const float*)d_in[12];
    const float* br2   = (const float*)d_in[13];
    const float* We2   = (const float*)d_in[14];
    const float* att2  = (const float*)d_in[15];
    const float* bias2 = (const float*)d_in[16];
    const float* w_ln1 = (const float*)d_in[17];
    const float* w_ln3 = (const float*)d_in[18];
    const float* W_out = (const float*)d_in[19];
    float* out = (float*)d_out;

    const int* srcp = ei;
    const int* dstp = ei + NE;

    float* xlr1 = (float*)sym(g_xlr1);
    float* acc1 = (float*)sym(g_acc1);
    float* xlr2 = (float*)sym(g_xlr2);
    float* acc2 = (float*)sym(g_acc2);
    int* deg    = (int*)sym(g_deg);
    int* off    = (int*)sym(g_off);
    int* cursor = (int*)sym(g_cursor);
    int* eid    = (int*)sym(g_eid);

    // 0-3: CSR build
    zero_deg_k<<<(NN + 255) / 256, 256>>>(deg);
    hist_k<<<(NE + 255) / 256, 256>>>(dstp, deg);
    scan_k<<<1, 1024>>>(deg, off, cursor);
    scatter_k<<<(NE + 255) / 256, 256>>>(dstp, cursor, eid);

    // 4: layer 1 fused transforms: xlr1[N,1024] = x @ [Wl1|Wr1]^T + [bl1|br1]
    dim3 g1(2 * D1 / 64, (NN + 127) / 128);
    gemm_tc2_k<<<g1, 256>>>(x, Wl1, Wr1, bl1, br1, xlr1, NN, D1, D2);

    // 5: CSR edge pass layer 1 (ncu -s 5)
    gat_edge1_k<<<(NN * H * 32 + 255) / 256, 256>>>(srcp, eattr, off, eid, xlr1, We1, att1, acc1);

    // 6: silu + rmsnorm
    postact_rms_k<<<NN, 256>>>(acc1, bias1, w_ln1, acc1, D1, 1);

    // 7: layer 2 fused transforms: xlr2[N,256] = acc1 @ [Wl2|Wr2]^T + ...
    dim3 g2(2 * D2 / 64, (NN + 127) / 128);
    gemm_tc2_k<<<g2, 256>>>(acc1, Wl2, Wr2, bl2, br2, xlr2, NN, D2, D1);

    // 8: CSR edge pass layer 2
    gat_edge2_k<<<(NN * 32 + 255) / 256, 256>>>(srcp, eattr, off, eid, xlr2, We2, att2, acc2);

    // 9: rmsnorm
    postact_rms_k<<<NN, 256>>>(acc2, bias2, w_ln3, acc2, D2, 0);

    // 10: classifier
    int ntot = NN * NCLS;
    out_gemm_k<<<(ntot + 255) / 256, 256, NCLS * D2 * sizeof(float)>>>(acc2, W_out, out, NN, D2, NCLS);
}